// round 14
// baseline (speedup 1.0000x reference)
#include <cuda_runtime.h>
#include <math.h>

#define B_  32
#define L_  512
#define D_  32
#define K_  6
#define O_  192
#define DM_ 512

typedef unsigned long long ull;

// ---------------- scratch (device globals) ----------------
__device__ float g_err[B_*D_*L_];      // (bd, l)
__device__ float g_ymean[B_*D_*O_];    // (bd, o)
__device__ float g_V[B_*D_*O_];        // (b,d,o)
__device__ float g_gl[B_*D_*2];        // gate logits (atomic-accumulated)
__device__ float g_psum[B_*D_];        // per-block BN partial sum
__device__ float g_psq[B_*D_];         // per-block BN partial sumsq

// ---------------- packed f32x2 helpers ----------------
#define MUL2(d,a,b)   asm("mul.rn.f32x2 %0, %1, %2;"      : "=l"(d) : "l"(a), "l"(b))
#define ADD2(d,a,b)   asm("add.rn.f32x2 %0, %1, %2;"      : "=l"(d) : "l"(a), "l"(b))
#define FMA2(d,a,b,c) asm("fma.rn.f32x2 %0, %1, %2, %3;"  : "=l"(d) : "l"(a), "l"(b), "l"(c))
#define PACK2(p,lo,hi)   asm("mov.b64 %0, {%1, %2};" : "=l"(p) : "f"(lo), "f"(hi))
#define UNPACK2(lo,hi,p) asm("mov.b64 {%0, %1}, %2;" : "=f"(lo), "=f"(hi) : "l"(p))
#define EX2(d,s)      asm("ex2.approx.f32 %0, %1;"        : "=f"(d) : "f"(s))

// ---------------- warp-register bitonic sort of 512 elems ----------------
__device__ __forceinline__ void warp_sort512(float v[16], int lane) {
    #pragma unroll
    for (int lsz = 1; lsz <= 9; lsz++) {
        const int size = 1 << lsz;
        #pragma unroll
        for (int s = size >> 1; s >= 16; s >>= 1) {
            const int plane = s >> 4;
            const bool up   = (lane & plane) == 0;
            const bool desc = (lane & (size >> 4)) != 0;
            const bool keepmin = (up != desc);
            #pragma unroll
            for (int i = 0; i < 16; i++) {
                float o = __shfl_xor_sync(0xffffffffu, v[i], plane);
                v[i] = keepmin ? fminf(v[i], o) : fmaxf(v[i], o);
            }
        }
        #pragma unroll
        for (int s = (size >= 32 ? 8 : size >> 1); s >= 1; s >>= 1) {
            #pragma unroll
            for (int i = 0; i < 16; i++) {
                if ((i & s) == 0) {
                    const bool desc = (size >= 16) ? ((lane & (size >> 4)) != 0)
                                                   : ((i & size) != 0);
                    float a = v[i], b = v[i | s];
                    float lo = fminf(a, b), hi = fmaxf(a, b);
                    v[i]     = desc ? hi : lo;
                    v[i | s] = desc ? lo : hi;
                }
            }
        }
    }
}

// ---------------- kernel 1: fused stats + map + attention + BN partials ----------------
// one block per (b,d); 256 threads = 8 warps; 2 blocks/SM (128 regs, no spill).
// Attention: warp-pair split, x resident in regs, packed f32x2 accumulation.
__global__ void __launch_bounds__(256, 2) fused_kernel(const float* __restrict__ x,
                                                       const float* __restrict__ x_date,
                                                       const float* __restrict__ y_date) {
    __shared__ __align__(16) float sxd[K_][L_];   // x_date, mapped in place (12 KB)
    __shared__ __align__(16) float sx[L_];        // x column (2 KB)
    __shared__ float syd[O_][K_];                 // raw y_date staging (4.5 KB)
    __shared__ ull   sydd[O_][K_];                // mapped y * CSC dup-packed (9 KB)
    __shared__ float sps[O_*2], spv[O_*2];        // per (o, half) partials (3 KB)
    __shared__ float sV[O_];
    __shared__ float smed[8], ssd[8];
    __shared__ float ssc[K_], ssh[K_];

    const int bd = blockIdx.x, tid = threadIdx.x;
    const int b = bd >> 5, d = bd & 31;
    const int warp = tid >> 5, lane = tid & 31;
    const float CSC = 0.408248290463863f * 1.4426950408889634f;  // 1/sqrt6 * log2e

    // zero gate-logit accumulators (mlp1 runs strictly after this kernel)
    if (bd < 8) g_gl[bd*256 + tid] = 0.0f;

    // ---- stage x_date: 2 l-rows per thread, 3 float2 each ----
    {
        const float* xb = x_date + (size_t)b*L_*D_*K_ + (size_t)d*K_;
        const int l0 = tid*2;
        const float2* q0 = reinterpret_cast<const float2*>(xb + (size_t)l0*(D_*K_));
        const float2* q1 = reinterpret_cast<const float2*>(xb + (size_t)(l0+1)*(D_*K_));
        float2 a0 = q0[0], a1 = q0[1], a2 = q0[2];
        float2 c0 = q1[0], c1 = q1[1], c2 = q1[2];
        sxd[0][l0]   = a0.x; sxd[1][l0]   = a0.y; sxd[2][l0]   = a1.x;
        sxd[3][l0]   = a1.y; sxd[4][l0]   = a2.x; sxd[5][l0]   = a2.y;
        sxd[0][l0+1] = c0.x; sxd[1][l0+1] = c0.y; sxd[2][l0+1] = c1.x;
        sxd[3][l0+1] = c1.y; sxd[4][l0+1] = c2.x; sxd[5][l0+1] = c2.y;
    }
    sx[tid]       = x[((size_t)b*L_ + tid)*D_ + d];
    sx[tid + 256] = x[((size_t)b*L_ + tid + 256)*D_ + d];

    // ---- stage y_date raw into smem ----
    if (tid < O_) {
        const float* yb = y_date + (size_t)b*O_*D_*K_ + (size_t)d*K_ + (size_t)tid*(D_*K_);
        const float2* q = reinterpret_cast<const float2*>(yb);
        float2 c0 = q[0], c1 = q[1], c2 = q[2];
        syd[tid][0] = c0.x; syd[tid][1] = c0.y; syd[tid][2] = c1.x;
        syd[tid][3] = c1.y; syd[tid][4] = c2.x; syd[tid][5] = c2.y;
    }
    __syncthreads();

    // ---- sort: warps 0..5 -> x_date[:,k], warp 6 -> x ----
    if (warp < 7) {
        float v[16];
        const float* src = (warp < 6) ? sxd[warp] : sx;
        #pragma unroll
        for (int i = 0; i < 16; i++) v[i] = src[lane + 32*i];   // conflict-free
        warp_sort512(v, lane);
        const float e127 = __shfl_sync(0xffffffffu, v[15], 7);
        const float e128 = __shfl_sync(0xffffffffu, v[0],  8);
        const float e255 = __shfl_sync(0xffffffffu, v[15], 15);
        const float e383 = __shfl_sync(0xffffffffu, v[15], 23);
        const float e384 = __shfl_sync(0xffffffffu, v[0],  24);
        if (lane == 0) {
            const float q75 = e383 + 0.25f * (e384 - e383);    // pos 383.25
            const float q25 = e127 + 0.75f * (e128 - e127);    // pos 127.75
            smed[warp] = e255;                                 // torch lower-median
            ssd[warp]  = q75 - q25 + 1e-6f;
        }
    }
    __syncthreads();
    if (tid < K_) {
        float sc = ssd[6] / ssd[tid];
        ssc[tid] = sc;
        ssh[tid] = smed[6] - smed[tid] * sc;
    }
    __syncthreads();

    // ---- map y: syd -> ymean + dup-packed sydd ----
    if (tid < O_) {
        float s = 0.f;
        #pragma unroll
        for (int k = 0; k < K_; k++) {
            float m = fmaf(syd[tid][k], ssc[k], ssh[k]);
            s += m;
            float t = m * CSC;
            ull p; PACK2(p, t, t);
            sydd[tid][k] = p;
        }
        g_ymean[(size_t)bd*O_ + tid] = s * (1.0f/6.0f);
    }

    // ---- map x_date in place + err (same-thread l's) ----
    #pragma unroll
    for (int rep = 0; rep < 2; rep++) {
        const int l = tid + rep*256;
        float s = 0.f;
        #pragma unroll
        for (int k = 0; k < K_; k++) {
            float m = fmaf(sxd[k][l], ssc[k], ssh[k]);
            sxd[k][l] = m;
            s += m;
        }
        g_err[(size_t)bd*L_ + l] = sx[l] - s * (1.0f/6.0f);
    }
    __syncthreads();

    // ---- attention: warp-pair p owns 48 o's; half h owns 256 l's IN REGS ----
    {
        const int h = warp & 1, p = warp >> 1;

        // load x chunk ONCE: 4 l-pairs per lane (8 l's), conflict-free LDS.64
        ull xk2[4][K_];
        ull xq[4];
        #pragma unroll
        for (int j = 0; j < 4; j++) {
            const int l = h*256 + j*64 + lane*2;
            #pragma unroll
            for (int k = 0; k < K_; k++)
                xk2[j][k] = *reinterpret_cast<const ull*>(&sxd[k][l]);
            xq[j] = *reinterpret_cast<const ull*>(&sx[l]);
        }

        // 24 iterations of 2 interleaved o's; packed f32x2 accumulators
        #pragma unroll 1
        for (int ot = 0; ot < 24; ot++) {
            const int o0 = p*48 + ot*2;
            const ull* ypA = sydd[o0];
            const ull* ypB = sydd[o0 + 1];
            ull sumA = 0, vsA = 0, sumB = 0, vsB = 0;
            #pragma unroll
            for (int j = 0; j < 4; j++) {
                ull a, c;
                MUL2(a, xk2[j][0], ypA[0]);
                MUL2(c, xk2[j][0], ypB[0]);
                FMA2(a, xk2[j][1], ypA[1], a);
                FMA2(c, xk2[j][1], ypB[1], c);
                FMA2(a, xk2[j][2], ypA[2], a);
                FMA2(c, xk2[j][2], ypB[2], c);
                FMA2(a, xk2[j][3], ypA[3], a);
                FMA2(c, xk2[j][3], ypB[3], c);
                FMA2(a, xk2[j][4], ypA[4], a);
                FMA2(c, xk2[j][4], ypB[4], c);
                FMA2(a, xk2[j][5], ypA[5], a);
                FMA2(c, xk2[j][5], ypB[5], c);
                float sa0, sa1, sb0, sb1;
                UNPACK2(sa0, sa1, a);
                UNPACK2(sb0, sb1, c);
                float ea0, ea1, eb0, eb1;
                EX2(ea0, sa0); EX2(ea1, sa1);
                EX2(eb0, sb0); EX2(eb1, sb1);
                ull ppA, ppB;
                PACK2(ppA, ea0, ea1);
                PACK2(ppB, eb0, eb1);
                ADD2(sumA, sumA, ppA);
                FMA2(vsA, ppA, xq[j], vsA);
                ADD2(sumB, sumB, ppB);
                FMA2(vsB, ppB, xq[j], vsB);
            }
            // combine packed halves -> scalars, then two shfl-reduce chains
            float t0, t1;
            UNPACK2(t0, t1, sumA);  float sA = t0 + t1;
            UNPACK2(t0, t1, vsA);   float vA = t0 + t1;
            UNPACK2(t0, t1, sumB);  float sB = t0 + t1;
            UNPACK2(t0, t1, vsB);   float vB = t0 + t1;
            #pragma unroll
            for (int off = 16; off; off >>= 1) {
                sA += __shfl_xor_sync(0xffffffffu, sA, off);
                sB += __shfl_xor_sync(0xffffffffu, sB, off);
                vA += __shfl_xor_sync(0xffffffffu, vA, off);
                vB += __shfl_xor_sync(0xffffffffu, vB, off);
            }
            if (lane == 0) {
                sps[o0*2 + h]     = sA;
                spv[o0*2 + h]     = vA;
                sps[(o0+1)*2 + h] = sB;
                spv[(o0+1)*2 + h] = vB;
            }
        }
    }
    __syncthreads();

    // ---- combine halves -> V ----
    if (tid < O_) {
        float s = sps[tid*2] + sps[tid*2 + 1];
        float v = spv[tid*2] + spv[tid*2 + 1];
        float r = v / s;
        g_V[(size_t)bd*O_ + tid] = r;
        sV[tid] = r;
    }
    __syncthreads();

    // ---- BN partials over this block's 192 o-values ----
    if (warp == 0) {
        float s = 0.f, sq = 0.f;
        for (int o = lane; o < O_; o += 32) {
            float v = sV[o];
            s += v;
            sq = fmaf(v, v, sq);
        }
        #pragma unroll
        for (int off = 16; off; off >>= 1) {
            s  += __shfl_xor_sync(0xffffffffu, s,  off);
            sq += __shfl_xor_sync(0xffffffffu, sq, off);
        }
        if (lane == 0) { g_psum[bd] = s; g_psq[bd] = sq; }
    }
}

// ---------------- kernel 2: f32x2 GEMM, 32x64 tiles, transposed Es ----------------
// grid (DM/64=8, BD/32=32) = 256 blocks, 256 threads.
__global__ void __launch_bounds__(256) mlp1_kernel(const float* __restrict__ w1,
                                                   const float* __restrict__ b1,
                                                   const float* __restrict__ w2) {
    __shared__ float Est[16][34];                 // [kk][row], padded
    __shared__ __align__(16) float Ws[16][64];    // [kk][col]
    const int tid = threadIdx.x;
    const int tx = tid & 15, ty = tid >> 4;       // 16 col-groups x 16 row-groups
    const int row0 = blockIdx.y * 32, col0 = blockIdx.x * 64;
    ull acc2[2][2] = {};                          // 2 rows x 2 f32x2 col-pairs

    for (int k0 = 0; k0 < 512; k0 += 16) {
        __syncthreads();
        {
            // Es_t: 16 kk x 32 rows; thread loads float2 of kk, writes transposed
            const int r = tid >> 3, kkb = (tid & 7) * 2;
            const float2 e2 = *reinterpret_cast<const float2*>(
                &g_err[(size_t)(row0 + r)*512 + k0 + kkb]);
            Est[kkb][r]     = e2.x;
            Est[kkb + 1][r] = e2.y;
            // Ws: 16 kk x 64 cols; thread loads float4 of cols
            const int kw = tid >> 4, c4 = (tid & 15) * 4;
            *reinterpret_cast<float4*>(&Ws[kw][c4]) =
                *reinterpret_cast<const float4*>(&w1[(size_t)(k0 + kw)*512 + col0 + c4]);
        }
        __syncthreads();
        #pragma unroll
        for (int kk = 0; kk < 16; kk++) {
            const ulonglong2 wv = *reinterpret_cast<const ulonglong2*>(&Ws[kk][tx*4]);
            const float2 ev = *reinterpret_cast<const float2*>(&Est[kk][ty*2]);
            ull a0; PACK2(a0, ev.x, ev.x);
            ull a1; PACK2(a1, ev.y, ev.y);
            FMA2(acc2[0][0], a0, wv.x, acc2[0][0]);
            FMA2(acc2[0][1], a0, wv.y, acc2[0][1]);
            FMA2(acc2[1][0], a1, wv.x, acc2[1][0]);
            FMA2(acc2[1][1], a1, wv.y, acc2[1][1]);
        }
    }
    #pragma unroll
    for (int i = 0; i < 2; i++) {
        const int row = row0 + ty*2 + i;
        float p0 = 0.f, p1 = 0.f;
        #pragma unroll
        for (int j = 0; j < 2; j++) {
            float c0, c1; UNPACK2(c0, c1, acc2[i][j]);
            #pragma unroll
            for (int hh = 0; hh < 2; hh++) {
                const int col = col0 + tx*4 + 2*j + hh;
                float v = (hh ? c1 : c0) + b1[col];
                float g = 0.5f * v * (1.0f + erff(v * 0.7071067811865476f));
                p0 = fmaf(g, w2[col*2 + 0], p0);
                p1 = fmaf(g, w2[col*2 + 1], p1);
            }
        }
        // reduce over the 16 tx-lanes (same ty within warp)
        #pragma unroll
        for (int off = 8; off; off >>= 1) {
            p0 += __shfl_xor_sync(0xffffffffu, p0, off);
            p1 += __shfl_xor_sync(0xffffffffu, p1, off);
        }
        if (tx == 0) {
            atomicAdd(&g_gl[row*2 + 0], p0);
            atomicAdd(&g_gl[row*2 + 1], p1);
        }
    }
}

// ---------------- kernel 3: BN reduce (redundant) + apply + gate + fusion ----------------
__global__ void __launch_bounds__(256) final_kernel(const float* __restrict__ bn_gamma,
                                                    const float* __restrict__ bn_beta,
                                                    const float* __restrict__ b2,
                                                    float* __restrict__ out) {
    __shared__ float tV[32][33], tY[32][33];
    __shared__ float rs[8][32], rq[8][32];
    __shared__ float smu[32], srstd[32];
    const int b  = blockIdx.y;
    const int ot = blockIdx.x * 32;
    const int warp = threadIdx.x >> 5, lane = threadIdx.x & 31;

    {
        float s = 0.f, sq = 0.f;
        #pragma unroll
        for (int j = 0; j < 4; j++) {
            const int bb = warp + j*8;
            s  += g_psum[bb*D_ + lane];
            sq += g_psq[bb*D_ + lane];
        }
        rs[warp][lane] = s;
        rq[warp][lane] = sq;
    }

    #pragma unroll
    for (int i = 0; i < 4; i++) {
        const int d = warp*4 + i;
        const size_t base = ((size_t)(b*D_ + d))*O_ + ot + lane;
        tV[d][lane] = g_V[base];
        tY[d][lane] = g_ymean[base];
    }
    __syncthreads();

    if (threadIdx.x < 32) {
        float s = 0.f, sq = 0.f;
        #pragma unroll
        for (int w = 0; w < 8; w++) { s += rs[w][threadIdx.x]; sq += rq[w][threadIdx.x]; }
        float mu  = s * (1.0f / (B_*O_));
        float var = sq * (1.0f / (B_*O_)) - mu*mu;
        smu[threadIdx.x]   = mu;
        srstd[threadIdx.x] = rsqrtf(var + 1e-5f);
    }
    __syncthreads();

    const int bd = b*D_ + lane;
    float l0 = g_gl[bd*2 + 0] + b2[0];
    float l1 = g_gl[bd*2 + 1] + b2[1];
    float m  = fmaxf(l0, l1);
    float e0 = __expf(l0 - m), e1 = __expf(l1 - m);
    float inv = 1.0f / (e0 + e1);
    const float w0 = e0 * inv, w1 = e1 * inv;
    const float mu = smu[lane], rstd = srstd[lane];
    const float ga = bn_gamma[lane], be = bn_beta[lane];

    #pragma unroll
    for (int i = 0; i < 4; i++) {
        const int oc = warp*4 + i;
        float v  = tV[lane][oc];
        float ym = tY[lane][oc];
        float y  = fmaf((v - mu) * rstd, ga, be);
        out[((size_t)(b*O_ + ot + oc))*D_ + lane] = ym * w0 + y * w1;
    }
}

// ---------------- launch ----------------
extern "C" void kernel_launch(void* const* d_in, const int* in_sizes, int n_in,
                              void* d_out, int out_size) {
    const float* x       = (const float*)d_in[0];
    const float* x_date  = (const float*)d_in[1];
    const float* y_date  = (const float*)d_in[2];
    const float* mlp_w1  = (const float*)d_in[3];
    const float* mlp_b1  = (const float*)d_in[4];
    const float* mlp_w2  = (const float*)d_in[5];
    const float* mlp_b2  = (const float*)d_in[6];
    const float* bn_gamma= (const float*)d_in[7];
    const float* bn_beta = (const float*)d_in[8];
    float* out = (float*)d_out;

    fused_kernel<<<B_*D_, 256>>>(x, x_date, y_date);
    mlp1_kernel<<<dim3(DM_/64, (B_*D_)/32), 256>>>(mlp_w1, mlp_b1, mlp_w2);
    final_kernel<<<dim3(O_/32, B_), 256>>>(bn_gamma, bn_beta, mlp_b2, out);
}

// round 15
// speedup vs baseline: 1.0210x; 1.0210x over previous
#include <cuda_runtime.h>
#include <math.h>

#define B_  32
#define L_  512
#define D_  32
#define K_  6
#define O_  192
#define DM_ 512

typedef unsigned long long ull;

// ---------------- scratch (device globals) ----------------
__device__ float g_err[B_*D_*L_];      // (bd, l)
__device__ float g_ymean[B_*D_*O_];    // (bd, o)
__device__ float g_V[B_*D_*O_];        // (b,d,o)
__device__ float g_gl[B_*D_*2];        // gate logits (atomic-accumulated)
__device__ float g_psum[B_*D_];        // per-block BN partial sum
__device__ float g_psq[B_*D_];         // per-block BN partial sumsq

// ---------------- packed f32x2 helpers ----------------
#define MUL2(d,a,b)   asm("mul.rn.f32x2 %0, %1, %2;"      : "=l"(d) : "l"(a), "l"(b))
#define ADD2(d,a,b)   asm("add.rn.f32x2 %0, %1, %2;"      : "=l"(d) : "l"(a), "l"(b))
#define FMA2(d,a,b,c) asm("fma.rn.f32x2 %0, %1, %2, %3;"  : "=l"(d) : "l"(a), "l"(b), "l"(c))
#define PACK2(p,lo,hi)   asm("mov.b64 %0, {%1, %2};" : "=l"(p) : "f"(lo), "f"(hi))
#define UNPACK2(lo,hi,p) asm("mov.b64 {%0, %1}, %2;" : "=f"(lo), "=f"(hi) : "l"(p))
#define EX2(d,s)      asm("ex2.approx.f32 %0, %1;"        : "=f"(d) : "f"(s))

// ---------------- warp-register bitonic sort of 512 elems ----------------
__device__ __forceinline__ void warp_sort512(float v[16], int lane) {
    #pragma unroll
    for (int lsz = 1; lsz <= 9; lsz++) {
        const int size = 1 << lsz;
        #pragma unroll
        for (int s = size >> 1; s >= 16; s >>= 1) {
            const int plane = s >> 4;
            const bool up   = (lane & plane) == 0;
            const bool desc = (lane & (size >> 4)) != 0;
            const bool keepmin = (up != desc);
            #pragma unroll
            for (int i = 0; i < 16; i++) {
                float o = __shfl_xor_sync(0xffffffffu, v[i], plane);
                v[i] = keepmin ? fminf(v[i], o) : fmaxf(v[i], o);
            }
        }
        #pragma unroll
        for (int s = (size >= 32 ? 8 : size >> 1); s >= 1; s >>= 1) {
            #pragma unroll
            for (int i = 0; i < 16; i++) {
                if ((i & s) == 0) {
                    const bool desc = (size >= 16) ? ((lane & (size >> 4)) != 0)
                                                   : ((i & size) != 0);
                    float a = v[i], b = v[i | s];
                    float lo = fminf(a, b), hi = fmaxf(a, b);
                    v[i]     = desc ? hi : lo;
                    v[i | s] = desc ? lo : hi;
                }
            }
        }
    }
}

// ---------------- kernel 1: fused stats + map + attention + BN partials ----------------
// one block per (b,d); 256 threads = 8 warps; 2 blocks/SM (128 regs, no spill).
// Attention: warp-pair split, x resident in regs, packed f32x2 accumulation.
__global__ void __launch_bounds__(256, 2) fused_kernel(const float* __restrict__ x,
                                                       const float* __restrict__ x_date,
                                                       const float* __restrict__ y_date) {
    __shared__ __align__(16) float sxd[K_][L_];   // x_date, mapped in place (12 KB)
    __shared__ __align__(16) float sx[L_];        // x column (2 KB)
    __shared__ float syd[O_][K_];                 // raw y_date staging (4.5 KB)
    __shared__ ull   sydd[O_][K_];                // mapped y * CSC dup-packed (9 KB)
    __shared__ float sps[O_*2], spv[O_*2];        // per (o, half) partials (3 KB)
    __shared__ float sV[O_];
    __shared__ float smed[8], ssd[8];
    __shared__ float ssc[K_], ssh[K_];

    const int bd = blockIdx.x, tid = threadIdx.x;
    const int b = bd >> 5, d = bd & 31;
    const int warp = tid >> 5, lane = tid & 31;
    const float CSC = 0.408248290463863f * 1.4426950408889634f;  // 1/sqrt6 * log2e

    // zero gate-logit accumulators (mlp1 runs strictly after this kernel)
    if (bd < 8) g_gl[bd*256 + tid] = 0.0f;

    // ---- stage x_date: 2 l-rows per thread, 3 float2 each ----
    {
        const float* xb = x_date + (size_t)b*L_*D_*K_ + (size_t)d*K_;
        const int l0 = tid*2;
        const float2* q0 = reinterpret_cast<const float2*>(xb + (size_t)l0*(D_*K_));
        const float2* q1 = reinterpret_cast<const float2*>(xb + (size_t)(l0+1)*(D_*K_));
        float2 a0 = q0[0], a1 = q0[1], a2 = q0[2];
        float2 c0 = q1[0], c1 = q1[1], c2 = q1[2];
        sxd[0][l0]   = a0.x; sxd[1][l0]   = a0.y; sxd[2][l0]   = a1.x;
        sxd[3][l0]   = a1.y; sxd[4][l0]   = a2.x; sxd[5][l0]   = a2.y;
        sxd[0][l0+1] = c0.x; sxd[1][l0+1] = c0.y; sxd[2][l0+1] = c1.x;
        sxd[3][l0+1] = c1.y; sxd[4][l0+1] = c2.x; sxd[5][l0+1] = c2.y;
    }
    sx[tid]       = x[((size_t)b*L_ + tid)*D_ + d];
    sx[tid + 256] = x[((size_t)b*L_ + tid + 256)*D_ + d];

    // ---- stage y_date raw into smem ----
    if (tid < O_) {
        const float* yb = y_date + (size_t)b*O_*D_*K_ + (size_t)d*K_ + (size_t)tid*(D_*K_);
        const float2* q = reinterpret_cast<const float2*>(yb);
        float2 c0 = q[0], c1 = q[1], c2 = q[2];
        syd[tid][0] = c0.x; syd[tid][1] = c0.y; syd[tid][2] = c1.x;
        syd[tid][3] = c1.y; syd[tid][4] = c2.x; syd[tid][5] = c2.y;
    }
    __syncthreads();

    // ---- sort: warps 0..5 -> x_date[:,k], warp 6 -> x ----
    if (warp < 7) {
        float v[16];
        const float* src = (warp < 6) ? sxd[warp] : sx;
        #pragma unroll
        for (int i = 0; i < 16; i++) v[i] = src[lane + 32*i];   // conflict-free
        warp_sort512(v, lane);
        const float e127 = __shfl_sync(0xffffffffu, v[15], 7);
        const float e128 = __shfl_sync(0xffffffffu, v[0],  8);
        const float e255 = __shfl_sync(0xffffffffu, v[15], 15);
        const float e383 = __shfl_sync(0xffffffffu, v[15], 23);
        const float e384 = __shfl_sync(0xffffffffu, v[0],  24);
        if (lane == 0) {
            const float q75 = e383 + 0.25f * (e384 - e383);    // pos 383.25
            const float q25 = e127 + 0.75f * (e128 - e127);    // pos 127.75
            smed[warp] = e255;                                 // torch lower-median
            ssd[warp]  = q75 - q25 + 1e-6f;
        }
    }
    __syncthreads();
    if (tid < K_) {
        float sc = ssd[6] / ssd[tid];
        ssc[tid] = sc;
        ssh[tid] = smed[6] - smed[tid] * sc;
    }
    __syncthreads();

    // ---- map y: syd -> ymean + dup-packed sydd ----
    if (tid < O_) {
        float s = 0.f;
        #pragma unroll
        for (int k = 0; k < K_; k++) {
            float m = fmaf(syd[tid][k], ssc[k], ssh[k]);
            s += m;
            float t = m * CSC;
            ull p; PACK2(p, t, t);
            sydd[tid][k] = p;
        }
        g_ymean[(size_t)bd*O_ + tid] = s * (1.0f/6.0f);
    }

    // ---- map x_date in place + err (same-thread l's) ----
    #pragma unroll
    for (int rep = 0; rep < 2; rep++) {
        const int l = tid + rep*256;
        float s = 0.f;
        #pragma unroll
        for (int k = 0; k < K_; k++) {
            float m = fmaf(sxd[k][l], ssc[k], ssh[k]);
            sxd[k][l] = m;
            s += m;
        }
        g_err[(size_t)bd*L_ + l] = sx[l] - s * (1.0f/6.0f);
    }
    __syncthreads();

    // ---- attention: warp-pair p owns 48 o's; half h owns 256 l's IN REGS ----
    {
        const int h = warp & 1, p = warp >> 1;

        // load x chunk ONCE: 4 l-pairs per lane (8 l's), conflict-free LDS.64
        ull xk2[4][K_];
        ull xq[4];
        #pragma unroll
        for (int j = 0; j < 4; j++) {
            const int l = h*256 + j*64 + lane*2;
            #pragma unroll
            for (int k = 0; k < K_; k++)
                xk2[j][k] = *reinterpret_cast<const ull*>(&sxd[k][l]);
            xq[j] = *reinterpret_cast<const ull*>(&sx[l]);
        }

        // 24 iterations of 2 interleaved o's; packed f32x2 accumulators
        #pragma unroll 1
        for (int ot = 0; ot < 24; ot++) {
            const int o0 = p*48 + ot*2;
            const ull* ypA = sydd[o0];
            const ull* ypB = sydd[o0 + 1];
            ull sumA = 0, vsA = 0, sumB = 0, vsB = 0;
            #pragma unroll
            for (int j = 0; j < 4; j++) {
                ull a, c;
                MUL2(a, xk2[j][0], ypA[0]);
                MUL2(c, xk2[j][0], ypB[0]);
                FMA2(a, xk2[j][1], ypA[1], a);
                FMA2(c, xk2[j][1], ypB[1], c);
                FMA2(a, xk2[j][2], ypA[2], a);
                FMA2(c, xk2[j][2], ypB[2], c);
                FMA2(a, xk2[j][3], ypA[3], a);
                FMA2(c, xk2[j][3], ypB[3], c);
                FMA2(a, xk2[j][4], ypA[4], a);
                FMA2(c, xk2[j][4], ypB[4], c);
                FMA2(a, xk2[j][5], ypA[5], a);
                FMA2(c, xk2[j][5], ypB[5], c);
                float sa0, sa1, sb0, sb1;
                UNPACK2(sa0, sa1, a);
                UNPACK2(sb0, sb1, c);
                float ea0, ea1, eb0, eb1;
                EX2(ea0, sa0); EX2(ea1, sa1);
                EX2(eb0, sb0); EX2(eb1, sb1);
                ull ppA, ppB;
                PACK2(ppA, ea0, ea1);
                PACK2(ppB, eb0, eb1);
                ADD2(sumA, sumA, ppA);
                FMA2(vsA, ppA, xq[j], vsA);
                ADD2(sumB, sumB, ppB);
                FMA2(vsB, ppB, xq[j], vsB);
            }
            // combine packed halves -> scalars, then two shfl-reduce chains
            float t0, t1;
            UNPACK2(t0, t1, sumA);  float sA = t0 + t1;
            UNPACK2(t0, t1, vsA);   float vA = t0 + t1;
            UNPACK2(t0, t1, sumB);  float sB = t0 + t1;
            UNPACK2(t0, t1, vsB);   float vB = t0 + t1;
            #pragma unroll
            for (int off = 16; off; off >>= 1) {
                sA += __shfl_xor_sync(0xffffffffu, sA, off);
                sB += __shfl_xor_sync(0xffffffffu, sB, off);
                vA += __shfl_xor_sync(0xffffffffu, vA, off);
                vB += __shfl_xor_sync(0xffffffffu, vB, off);
            }
            if (lane == 0) {
                sps[o0*2 + h]     = sA;
                spv[o0*2 + h]     = vA;
                sps[(o0+1)*2 + h] = sB;
                spv[(o0+1)*2 + h] = vB;
            }
        }
    }
    __syncthreads();

    // ---- combine halves -> V ----
    if (tid < O_) {
        float s = sps[tid*2] + sps[tid*2 + 1];
        float v = spv[tid*2] + spv[tid*2 + 1];
        float r = v / s;
        g_V[(size_t)bd*O_ + tid] = r;
        sV[tid] = r;
    }
    __syncthreads();

    // ---- BN partials over this block's 192 o-values ----
    if (warp == 0) {
        float s = 0.f, sq = 0.f;
        for (int o = lane; o < O_; o += 32) {
            float v = sV[o];
            s += v;
            sq = fmaf(v, v, sq);
        }
        #pragma unroll
        for (int off = 16; off; off >>= 1) {
            s  += __shfl_xor_sync(0xffffffffu, s,  off);
            sq += __shfl_xor_sync(0xffffffffu, sq, off);
        }
        if (lane == 0) { g_psum[bd] = s; g_psq[bd] = sq; }
    }
}

// ---------------- kernel 2: f32x2 GEMM (64x64, double-buffered loads) + gelu + gate ----------------
__global__ void __launch_bounds__(256) mlp1_kernel(const float* __restrict__ w1,
                                                   const float* __restrict__ b1,
                                                   const float* __restrict__ w2) {
    __shared__ float Es[64][17];
    __shared__ __align__(16) float Ws[16][64];
    const int tx = threadIdx.x & 15, ty = threadIdx.x >> 4;
    const int row0 = blockIdx.y * 64, col0 = blockIdx.x * 64;
    ull acc2[4][2] = {};

    // per-thread load coordinates (constant across iterations)
    int er[4], ek[4], wk[4], wc[4];
    #pragma unroll
    for (int it = 0; it < 4; it++) {
        int idx = threadIdx.x + it*256;
        er[it] = idx >> 4; ek[it] = idx & 15;
        wk[it] = idx >> 6; wc[it] = idx & 63;
    }

    // prefetch tile k0 = 0
    float eR[4], wR[4];
    #pragma unroll
    for (int it = 0; it < 4; it++) {
        eR[it] = g_err[(size_t)(row0 + er[it])*512 + ek[it]];
        wR[it] = w1[(size_t)wk[it]*512 + col0 + wc[it]];
    }

    for (int k0 = 0; k0 < 512; k0 += 16) {
        __syncthreads();
        #pragma unroll
        for (int it = 0; it < 4; it++) {
            Es[er[it]][ek[it]] = eR[it];
            Ws[wk[it]][wc[it]] = wR[it];
        }
        __syncthreads();
        // prefetch next tile while computing this one
        if (k0 + 16 < 512) {
            #pragma unroll
            for (int it = 0; it < 4; it++) {
                eR[it] = g_err[(size_t)(row0 + er[it])*512 + k0 + 16 + ek[it]];
                wR[it] = w1[(size_t)(k0 + 16 + wk[it])*512 + col0 + wc[it]];
            }
        }
        #pragma unroll
        for (int kk = 0; kk < 16; kk++) {
            const ull* wp = reinterpret_cast<const ull*>(&Ws[kk][tx*4]);
            const ull w0 = wp[0], w1v = wp[1];
            #pragma unroll
            for (int i = 0; i < 4; i++) {
                float a = Es[ty*4 + i][kk];
                ull ad; PACK2(ad, a, a);
                FMA2(acc2[i][0], ad, w0,  acc2[i][0]);
                FMA2(acc2[i][1], ad, w1v, acc2[i][1]);
            }
        }
    }
    #pragma unroll
    for (int i = 0; i < 4; i++) {
        const int row = row0 + ty*4 + i;
        float p0 = 0.f, p1 = 0.f;
        #pragma unroll
        for (int j = 0; j < 2; j++) {
            float c0, c1; UNPACK2(c0, c1, acc2[i][j]);
            #pragma unroll
            for (int h = 0; h < 2; h++) {
                const int col = col0 + tx*4 + 2*j + h;
                float v = (h ? c1 : c0) + b1[col];
                float g = 0.5f * v * (1.0f + erff(v * 0.7071067811865476f));
                p0 = fmaf(g, w2[col*2 + 0], p0);
                p1 = fmaf(g, w2[col*2 + 1], p1);
            }
        }
        #pragma unroll
        for (int off = 8; off; off >>= 1) {
            p0 += __shfl_xor_sync(0xffffffffu, p0, off);
            p1 += __shfl_xor_sync(0xffffffffu, p1, off);
        }
        if (tx == 0) {
            atomicAdd(&g_gl[row*2 + 0], p0);
            atomicAdd(&g_gl[row*2 + 1], p1);
        }
    }
}

// ---------------- kernel 3: BN reduce (redundant) + apply + gate + fusion ----------------
__global__ void __launch_bounds__(256) final_kernel(const float* __restrict__ bn_gamma,
                                                    const float* __restrict__ bn_beta,
                                                    const float* __restrict__ b2,
                                                    float* __restrict__ out) {
    __shared__ float tV[32][33], tY[32][33];
    __shared__ float rs[8][32], rq[8][32];
    __shared__ float smu[32], srstd[32];
    const int b  = blockIdx.y;
    const int ot = blockIdx.x * 32;
    const int warp = threadIdx.x >> 5, lane = threadIdx.x & 31;

    {
        float s = 0.f, sq = 0.f;
        #pragma unroll
        for (int j = 0; j < 4; j++) {
            const int bb = warp + j*8;
            s  += g_psum[bb*D_ + lane];
            sq += g_psq[bb*D_ + lane];
        }
        rs[warp][lane] = s;
        rq[warp][lane] = sq;
    }

    #pragma unroll
    for (int i = 0; i < 4; i++) {
        const int d = warp*4 + i;
        const size_t base = ((size_t)(b*D_ + d))*O_ + ot + lane;
        tV[d][lane] = g_V[base];
        tY[d][lane] = g_ymean[base];
    }
    __syncthreads();

    if (threadIdx.x < 32) {
        float s = 0.f, sq = 0.f;
        #pragma unroll
        for (int w = 0; w < 8; w++) { s += rs[w][threadIdx.x]; sq += rq[w][threadIdx.x]; }
        float mu  = s * (1.0f / (B_*O_));
        float var = sq * (1.0f / (B_*O_)) - mu*mu;
        smu[threadIdx.x]   = mu;
        srstd[threadIdx.x] = rsqrtf(var + 1e-5f);
    }
    __syncthreads();

    const int bd = b*D_ + lane;
    float l0 = g_gl[bd*2 + 0] + b2[0];
    float l1 = g_gl[bd*2 + 1] + b2[1];
    float m  = fmaxf(l0, l1);
    float e0 = __expf(l0 - m), e1 = __expf(l1 - m);
    float inv = 1.0f / (e0 + e1);
    const float w0 = e0 * inv, w1 = e1 * inv;
    const float mu = smu[lane], rstd = srstd[lane];
    const float ga = bn_gamma[lane], be = bn_beta[lane];

    #pragma unroll
    for (int i = 0; i < 4; i++) {
        const int oc = warp*4 + i;
        float v  = tV[lane][oc];
        float ym = tY[lane][oc];
        float y  = fmaf((v - mu) * rstd, ga, be);
        out[((size_t)(b*O_ + ot + oc))*D_ + lane] = ym * w0 + y * w1;
    }
}

// ---------------- launch ----------------
extern "C" void kernel_launch(void* const* d_in, const int* in_sizes, int n_in,
                              void* d_out, int out_size) {
    const float* x       = (const float*)d_in[0];
    const float* x_date  = (const float*)d_in[1];
    const float* y_date  = (const float*)d_in[2];
    const float* mlp_w1  = (const float*)d_in[3];
    const float* mlp_b1  = (const float*)d_in[4];
    const float* mlp_w2  = (const float*)d_in[5];
    const float* mlp_b2  = (const float*)d_in[6];
    const float* bn_gamma= (const float*)d_in[7];
    const float* bn_beta = (const float*)d_in[8];
    float* out = (float*)d_out;

    fused_kernel<<<B_*D_, 256>>>(x, x_date, y_date);
    mlp1_kernel<<<dim3(DM_/64, (B_*D_)/64), 256>>>(mlp_w1, mlp_b1, mlp_w2);
    final_kernel<<<dim3(O_/32, B_), 256>>>(bn_gamma, bn_beta, mlp_b2, out);
}

// round 16
// speedup vs baseline: 1.0417x; 1.0203x over previous
#include <cuda_runtime.h>
#include <math.h>

#define B_  32
#define L_  512
#define D_  32
#define K_  6
#define O_  192
#define DM_ 512

typedef unsigned long long ull;

// ---------------- scratch (device globals) ----------------
__device__ float g_err[B_*D_*L_];      // (bd, l)
__device__ float g_ymean[B_*D_*O_];    // (bd, o)
__device__ float g_V[B_*D_*O_];        // (b,d,o)
__device__ float g_gl[B_*D_*2];        // gate logits (atomic-accumulated)
__device__ float g_psum[B_*D_];        // per-block BN partial sum
__device__ float g_psq[B_*D_];         // per-block BN partial sumsq

// ---------------- packed f32x2 helpers ----------------
#define MUL2(d,a,b)   asm("mul.rn.f32x2 %0, %1, %2;"      : "=l"(d) : "l"(a), "l"(b))
#define ADD2(d,a,b)   asm("add.rn.f32x2 %0, %1, %2;"      : "=l"(d) : "l"(a), "l"(b))
#define FMA2(d,a,b,c) asm("fma.rn.f32x2 %0, %1, %2, %3;"  : "=l"(d) : "l"(a), "l"(b), "l"(c))
#define PACK2(p,lo,hi)   asm("mov.b64 %0, {%1, %2};" : "=l"(p) : "f"(lo), "f"(hi))
#define UNPACK2(lo,hi,p) asm("mov.b64 {%0, %1}, %2;" : "=f"(lo), "=f"(hi) : "l"(p))
#define EX2(d,s)      asm("ex2.approx.f32 %0, %1;"        : "=f"(d) : "f"(s))

// ---------------- warp-register bitonic sort of 512 elems ----------------
__device__ __forceinline__ void warp_sort512(float v[16], int lane) {
    #pragma unroll
    for (int lsz = 1; lsz <= 9; lsz++) {
        const int size = 1 << lsz;
        #pragma unroll
        for (int s = size >> 1; s >= 16; s >>= 1) {
            const int plane = s >> 4;
            const bool up   = (lane & plane) == 0;
            const bool desc = (lane & (size >> 4)) != 0;
            const bool keepmin = (up != desc);
            #pragma unroll
            for (int i = 0; i < 16; i++) {
                float o = __shfl_xor_sync(0xffffffffu, v[i], plane);
                v[i] = keepmin ? fminf(v[i], o) : fmaxf(v[i], o);
            }
        }
        #pragma unroll
        for (int s = (size >= 32 ? 8 : size >> 1); s >= 1; s >>= 1) {
            #pragma unroll
            for (int i = 0; i < 16; i++) {
                if ((i & s) == 0) {
                    const bool desc = (size >= 16) ? ((lane & (size >> 4)) != 0)
                                                   : ((i & size) != 0);
                    float a = v[i], b = v[i | s];
                    float lo = fminf(a, b), hi = fmaxf(a, b);
                    v[i]     = desc ? hi : lo;
                    v[i | s] = desc ? lo : hi;
                }
            }
        }
    }
}

// ---------------- kernel 1: fused stats + map + attention + BN partials ----------------
// one block per (b,d); 256 threads = 8 warps; 2 blocks/SM (128 regs, no spill).
// Attention: warp-pair split, x resident in regs, packed f32x2 accumulation.
__global__ void __launch_bounds__(256, 2) fused_kernel(const float* __restrict__ x,
                                                       const float* __restrict__ x_date,
                                                       const float* __restrict__ y_date) {
    __shared__ __align__(16) float sxd[K_][L_];   // x_date, mapped in place (12 KB)
    __shared__ __align__(16) float sx[L_];        // x column (2 KB)
    __shared__ float syd[O_][K_];                 // raw y_date staging (4.5 KB)
    __shared__ ull   sydd[O_][K_];                // mapped y * CSC dup-packed (9 KB)
    __shared__ float sps[O_*2], spv[O_*2];        // per (o, half) partials (3 KB)
    __shared__ float sV[O_];
    __shared__ float smed[8], ssd[8];
    __shared__ float ssc[K_], ssh[K_];

    const int bd = blockIdx.x, tid = threadIdx.x;
    const int b = bd >> 5, d = bd & 31;
    const int warp = tid >> 5, lane = tid & 31;
    const float CSC = 0.408248290463863f * 1.4426950408889634f;  // 1/sqrt6 * log2e

    // zero gate-logit accumulators (mlp1 runs strictly after this kernel)
    if (bd < 8) g_gl[bd*256 + tid] = 0.0f;

    // ---- stage x_date: 2 l-rows per thread, 3 float2 each ----
    {
        const float* xb = x_date + (size_t)b*L_*D_*K_ + (size_t)d*K_;
        const int l0 = tid*2;
        const float2* q0 = reinterpret_cast<const float2*>(xb + (size_t)l0*(D_*K_));
        const float2* q1 = reinterpret_cast<const float2*>(xb + (size_t)(l0+1)*(D_*K_));
        float2 a0 = q0[0], a1 = q0[1], a2 = q0[2];
        float2 c0 = q1[0], c1 = q1[1], c2 = q1[2];
        sxd[0][l0]   = a0.x; sxd[1][l0]   = a0.y; sxd[2][l0]   = a1.x;
        sxd[3][l0]   = a1.y; sxd[4][l0]   = a2.x; sxd[5][l0]   = a2.y;
        sxd[0][l0+1] = c0.x; sxd[1][l0+1] = c0.y; sxd[2][l0+1] = c1.x;
        sxd[3][l0+1] = c1.y; sxd[4][l0+1] = c2.x; sxd[5][l0+1] = c2.y;
    }
    sx[tid]       = x[((size_t)b*L_ + tid)*D_ + d];
    sx[tid + 256] = x[((size_t)b*L_ + tid + 256)*D_ + d];

    // ---- stage y_date raw into smem ----
    if (tid < O_) {
        const float* yb = y_date + (size_t)b*O_*D_*K_ + (size_t)d*K_ + (size_t)tid*(D_*K_);
        const float2* q = reinterpret_cast<const float2*>(yb);
        float2 c0 = q[0], c1 = q[1], c2 = q[2];
        syd[tid][0] = c0.x; syd[tid][1] = c0.y; syd[tid][2] = c1.x;
        syd[tid][3] = c1.y; syd[tid][4] = c2.x; syd[tid][5] = c2.y;
    }
    __syncthreads();

    // ---- sort: warps 0..5 -> x_date[:,k], warp 6 -> x ----
    if (warp < 7) {
        float v[16];
        const float* src = (warp < 6) ? sxd[warp] : sx;
        #pragma unroll
        for (int i = 0; i < 16; i++) v[i] = src[lane + 32*i];   // conflict-free
        warp_sort512(v, lane);
        const float e127 = __shfl_sync(0xffffffffu, v[15], 7);
        const float e128 = __shfl_sync(0xffffffffu, v[0],  8);
        const float e255 = __shfl_sync(0xffffffffu, v[15], 15);
        const float e383 = __shfl_sync(0xffffffffu, v[15], 23);
        const float e384 = __shfl_sync(0xffffffffu, v[0],  24);
        if (lane == 0) {
            const float q75 = e383 + 0.25f * (e384 - e383);    // pos 383.25
            const float q25 = e127 + 0.75f * (e128 - e127);    // pos 127.75
            smed[warp] = e255;                                 // torch lower-median
            ssd[warp]  = q75 - q25 + 1e-6f;
        }
    }
    __syncthreads();
    if (tid < K_) {
        float sc = ssd[6] / ssd[tid];
        ssc[tid] = sc;
        ssh[tid] = smed[6] - smed[tid] * sc;
    }
    __syncthreads();

    // ---- map y: syd -> ymean + dup-packed sydd ----
    if (tid < O_) {
        float s = 0.f;
        #pragma unroll
        for (int k = 0; k < K_; k++) {
            float m = fmaf(syd[tid][k], ssc[k], ssh[k]);
            s += m;
            float t = m * CSC;
            ull p; PACK2(p, t, t);
            sydd[tid][k] = p;
        }
        g_ymean[(size_t)bd*O_ + tid] = s * (1.0f/6.0f);
    }

    // ---- map x_date in place + err (same-thread l's) ----
    #pragma unroll
    for (int rep = 0; rep < 2; rep++) {
        const int l = tid + rep*256;
        float s = 0.f;
        #pragma unroll
        for (int k = 0; k < K_; k++) {
            float m = fmaf(sxd[k][l], ssc[k], ssh[k]);
            sxd[k][l] = m;
            s += m;
        }
        g_err[(size_t)bd*L_ + l] = sx[l] - s * (1.0f/6.0f);
    }
    __syncthreads();

    // ---- attention: warp-pair p owns 48 o's; half h owns 256 l's IN REGS ----
    {
        const int h = warp & 1, p = warp >> 1;

        // load x chunk ONCE: 4 l-pairs per lane (8 l's), conflict-free LDS.64
        ull xk2[4][K_];
        ull xq[4];
        #pragma unroll
        for (int j = 0; j < 4; j++) {
            const int l = h*256 + j*64 + lane*2;
            #pragma unroll
            for (int k = 0; k < K_; k++)
                xk2[j][k] = *reinterpret_cast<const ull*>(&sxd[k][l]);
            xq[j] = *reinterpret_cast<const ull*>(&sx[l]);
        }

        // 24 iterations of 2 interleaved o's; packed f32x2 accumulators
        #pragma unroll 1
        for (int ot = 0; ot < 24; ot++) {
            const int o0 = p*48 + ot*2;
            const ull* ypA = sydd[o0];
            const ull* ypB = sydd[o0 + 1];
            ull sumA = 0, vsA = 0, sumB = 0, vsB = 0;
            #pragma unroll
            for (int j = 0; j < 4; j++) {
                ull a, c;
                MUL2(a, xk2[j][0], ypA[0]);
                MUL2(c, xk2[j][0], ypB[0]);
                FMA2(a, xk2[j][1], ypA[1], a);
                FMA2(c, xk2[j][1], ypB[1], c);
                FMA2(a, xk2[j][2], ypA[2], a);
                FMA2(c, xk2[j][2], ypB[2], c);
                FMA2(a, xk2[j][3], ypA[3], a);
                FMA2(c, xk2[j][3], ypB[3], c);
                FMA2(a, xk2[j][4], ypA[4], a);
                FMA2(c, xk2[j][4], ypB[4], c);
                FMA2(a, xk2[j][5], ypA[5], a);
                FMA2(c, xk2[j][5], ypB[5], c);
                float sa0, sa1, sb0, sb1;
                UNPACK2(sa0, sa1, a);
                UNPACK2(sb0, sb1, c);
                float ea0, ea1, eb0, eb1;
                EX2(ea0, sa0); EX2(ea1, sa1);
                EX2(eb0, sb0); EX2(eb1, sb1);
                ull ppA, ppB;
                PACK2(ppA, ea0, ea1);
                PACK2(ppB, eb0, eb1);
                ADD2(sumA, sumA, ppA);
                FMA2(vsA, ppA, xq[j], vsA);
                ADD2(sumB, sumB, ppB);
                FMA2(vsB, ppB, xq[j], vsB);
            }
            // combine packed halves -> scalars, then two shfl-reduce chains
            float t0, t1;
            UNPACK2(t0, t1, sumA);  float sA = t0 + t1;
            UNPACK2(t0, t1, vsA);   float vA = t0 + t1;
            UNPACK2(t0, t1, sumB);  float sB = t0 + t1;
            UNPACK2(t0, t1, vsB);   float vB = t0 + t1;
            #pragma unroll
            for (int off = 16; off; off >>= 1) {
                sA += __shfl_xor_sync(0xffffffffu, sA, off);
                sB += __shfl_xor_sync(0xffffffffu, sB, off);
                vA += __shfl_xor_sync(0xffffffffu, vA, off);
                vB += __shfl_xor_sync(0xffffffffu, vB, off);
            }
            if (lane == 0) {
                sps[o0*2 + h]     = sA;
                spv[o0*2 + h]     = vA;
                sps[(o0+1)*2 + h] = sB;
                spv[(o0+1)*2 + h] = vB;
            }
        }
    }
    __syncthreads();

    // ---- combine halves -> V ----
    if (tid < O_) {
        float s = sps[tid*2] + sps[tid*2 + 1];
        float v = spv[tid*2] + spv[tid*2 + 1];
        float r = v / s;
        g_V[(size_t)bd*O_ + tid] = r;
        sV[tid] = r;
    }
    __syncthreads();

    // ---- BN partials over this block's 192 o-values ----
    if (warp == 0) {
        float s = 0.f, sq = 0.f;
        for (int o = lane; o < O_; o += 32) {
            float v = sV[o];
            s += v;
            sq = fmaf(v, v, sq);
        }
        #pragma unroll
        for (int off = 16; off; off >>= 1) {
            s  += __shfl_xor_sync(0xffffffffu, s,  off);
            sq += __shfl_xor_sync(0xffffffffu, sq, off);
        }
        if (lane == 0) { g_psum[bd] = s; g_psq[bd] = sq; }
    }
}

// ---------------- kernel 2: f32x2 GEMM (64x64 tiles, plain) + gelu + gate ----------------
__global__ void __launch_bounds__(256) mlp1_kernel(const float* __restrict__ w1,
                                                   const float* __restrict__ b1,
                                                   const float* __restrict__ w2) {
    __shared__ float Es[64][17];
    __shared__ __align__(16) float Ws[16][64];
    const int tx = threadIdx.x & 15, ty = threadIdx.x >> 4;
    const int row0 = blockIdx.y * 64, col0 = blockIdx.x * 64;
    ull acc2[4][2] = {};

    for (int k0 = 0; k0 < 512; k0 += 16) {
        __syncthreads();
        #pragma unroll
        for (int it = 0; it < 4; it++) {
            int idx = threadIdx.x + it*256;
            int r  = idx >> 4, kk = idx & 15;
            Es[r][kk] = g_err[(size_t)(row0 + r)*512 + k0 + kk];
            int kw = idx >> 6, c = idx & 63;
            Ws[kw][c] = w1[(size_t)(k0 + kw)*512 + col0 + c];
        }
        __syncthreads();
        #pragma unroll
        for (int kk = 0; kk < 16; kk++) {
            const ull* wp = reinterpret_cast<const ull*>(&Ws[kk][tx*4]);
            const ull w0 = wp[0], w1v = wp[1];
            #pragma unroll
            for (int i = 0; i < 4; i++) {
                float a = Es[ty*4 + i][kk];
                ull ad; PACK2(ad, a, a);
                FMA2(acc2[i][0], ad, w0,  acc2[i][0]);
                FMA2(acc2[i][1], ad, w1v, acc2[i][1]);
            }
        }
    }
    #pragma unroll
    for (int i = 0; i < 4; i++) {
        const int row = row0 + ty*4 + i;
        float p0 = 0.f, p1 = 0.f;
        #pragma unroll
        for (int j = 0; j < 2; j++) {
            float c0, c1; UNPACK2(c0, c1, acc2[i][j]);
            #pragma unroll
            for (int h = 0; h < 2; h++) {
                const int col = col0 + tx*4 + 2*j + h;
                float v = (h ? c1 : c0) + b1[col];
                float g = 0.5f * v * (1.0f + erff(v * 0.7071067811865476f));
                p0 = fmaf(g, w2[col*2 + 0], p0);
                p1 = fmaf(g, w2[col*2 + 1], p1);
            }
        }
        #pragma unroll
        for (int off = 8; off; off >>= 1) {
            p0 += __shfl_xor_sync(0xffffffffu, p0, off);
            p1 += __shfl_xor_sync(0xffffffffu, p1, off);
        }
        if (tx == 0) {
            atomicAdd(&g_gl[row*2 + 0], p0);
            atomicAdd(&g_gl[row*2 + 1], p1);
        }
    }
}

// ---------------- kernel 3: BN reduce (redundant) + apply + gate + fusion ----------------
__global__ void __launch_bounds__(256) final_kernel(const float* __restrict__ bn_gamma,
                                                    const float* __restrict__ bn_beta,
                                                    const float* __restrict__ b2,
                                                    float* __restrict__ out) {
    __shared__ float tV[32][33], tY[32][33];
    __shared__ float rs[8][32], rq[8][32];
    __shared__ float smu[32], srstd[32];
    const int b  = blockIdx.y;
    const int ot = blockIdx.x * 32;
    const int warp = threadIdx.x >> 5, lane = threadIdx.x & 31;

    {
        float s = 0.f, sq = 0.f;
        #pragma unroll
        for (int j = 0; j < 4; j++) {
            const int bb = warp + j*8;
            s  += g_psum[bb*D_ + lane];
            sq += g_psq[bb*D_ + lane];
        }
        rs[warp][lane] = s;
        rq[warp][lane] = sq;
    }

    #pragma unroll
    for (int i = 0; i < 4; i++) {
        const int d = warp*4 + i;
        const size_t base = ((size_t)(b*D_ + d))*O_ + ot + lane;
        tV[d][lane] = g_V[base];
        tY[d][lane] = g_ymean[base];
    }
    __syncthreads();

    if (threadIdx.x < 32) {
        float s = 0.f, sq = 0.f;
        #pragma unroll
        for (int w = 0; w < 8; w++) { s += rs[w][threadIdx.x]; sq += rq[w][threadIdx.x]; }
        float mu  = s * (1.0f / (B_*O_));
        float var = sq * (1.0f / (B_*O_)) - mu*mu;
        smu[threadIdx.x]   = mu;
        srstd[threadIdx.x] = rsqrtf(var + 1e-5f);
    }
    __syncthreads();

    const int bd = b*D_ + lane;
    float l0 = g_gl[bd*2 + 0] + b2[0];
    float l1 = g_gl[bd*2 + 1] + b2[1];
    float m  = fmaxf(l0, l1);
    float e0 = __expf(l0 - m), e1 = __expf(l1 - m);
    float inv = 1.0f / (e0 + e1);
    const float w0 = e0 * inv, w1 = e1 * inv;
    const float mu = smu[lane], rstd = srstd[lane];
    const float ga = bn_gamma[lane], be = bn_beta[lane];

    #pragma unroll
    for (int i = 0; i < 4; i++) {
        const int oc = warp*4 + i;
        float v  = tV[lane][oc];
        float ym = tY[lane][oc];
        float y  = fmaf((v - mu) * rstd, ga, be);
        out[((size_t)(b*O_ + ot + oc))*D_ + lane] = ym * w0 + y * w1;
    }
}

// ---------------- launch ----------------
extern "C" void kernel_launch(void* const* d_in, const int* in_sizes, int n_in,
                              void* d_out, int out_size) {
    const float* x       = (const float*)d_in[0];
    const float* x_date  = (const float*)d_in[1];
    const float* y_date  = (const float*)d_in[2];
    const float* mlp_w1  = (const float*)d_in[3];
    const float* mlp_b1  = (const float*)d_in[4];
    const float* mlp_w2  = (const float*)d_in[5];
    const float* mlp_b2  = (const float*)d_in[6];
    const float* bn_gamma= (const float*)d_in[7];
    const float* bn_beta = (const float*)d_in[8];
    float* out = (float*)d_out;

    fused_kernel<<<B_*D_, 256>>>(x, x_date, y_date);
    mlp1_kernel<<<dim3(DM_/64, (B_*D_)/64), 256>>>(mlp_w1, mlp_b1, mlp_w2);
    final_kernel<<<dim3(O_/32, B_), 256>>>(bn_gamma, bn_beta, mlp_b2, out);
}